// round 10
// baseline (speedup 1.0000x reference)
#include <cuda_runtime.h>
#include <math.h>

// BezierRenderer: 16 batches, 512x512, 10 segments.
//  K1 setup <<<16, 256>>>: per-batch segment params + per-tile (64x16) masks.
//  K2 render <<<1184, 256>>>: PDL, persistent single-wave. Each block owns
//     3-4 tiles (stride 74 within its batch): zero-fills them before the grid
//     sync (overlaps setup), then loads all masks at once and recomputes only
//     active tiles (4 px/thread, 4 independent FMA chains).

#define NSEG    10
#define NBATCH  16
#define NTILES  (256 * NBATCH)
#define SIZEI   512
#define BPB     74                  // blocks per batch (74*16 = 1184)

struct SegParams {
    float4 seg[NSEG];        // {vy, vx, dy, dx}
    float  id2[NSEG];
    float  thick, invthick;
};

__device__ SegParams g_params[NBATCH];
__device__ unsigned int g_mask[NTILES];

// ---------------------------------------------------------------------------
// K1: setup. One block per batch: stroke points, segment params, tile masks.
// ---------------------------------------------------------------------------
__global__ void __launch_bounds__(256)
setup_kernel(const float* __restrict__ traj,
             const float* __restrict__ thk)
{
    __shared__ float s_py[NSEG + 1], s_px[NSEG + 1];
    __shared__ float s_vy[NSEG], s_vx[NSEG], s_dy[NSEG], s_dx[NSEG], s_id2[NSEG];
    __shared__ float s_thick;

    const int b   = blockIdx.x;
    const int tid = threadIdx.x;

    if (tid <= NSEG) {
        float sy, sx;
        if (tid < NSEG) {
            const int start[4] = {10, 6, 3, 0};
            sy = 0.f; sx = 0.f;
#pragma unroll
            for (int i = 0; i < 4; i++) {
                float n = (float)(start[i] + tid) - 9.5f;
                float w = 0.75f * expf(-0.125f * n * n);   // exp(-0.5*(n/2)^2)
                sy += traj[b * 8 + i]     * w;
                sx += traj[b * 8 + 4 + i] * w;
            }
        } else {
            sy = traj[b * 8 + 3];
            sx = traj[b * 8 + 7];
        }
        s_py[tid] = sy * 512.f;
        s_px[tid] = sx * 512.f;
    }
    if (tid == 0) {
        float th = 0.f;
#pragma unroll
        for (int k = 0; k < 4; k++) th += thk[b * 4 + k] * 2.f + 0.5f;
        float t2 = 2.f * th;
        s_thick = t2;
        g_params[b].thick    = t2;
        g_params[b].invthick = 1.f / t2;
    }
    __syncthreads();

    if (tid < NSEG) {
        float vy = s_py[tid], vx = s_px[tid];
        float dy = s_py[tid + 1] - vy;
        float dx = s_px[tid + 1] - vx;
        float id2 = 1.f / (dy * dy + dx * dx + 1e-5f);
        s_vy[tid] = vy;  s_vx[tid] = vx;
        s_dy[tid] = dy;  s_dx[tid] = dx;
        s_id2[tid] = id2;
        g_params[b].seg[tid] = make_float4(vy, vx, dy, dx);
        g_params[b].id2[tid] = id2;
    }
    __syncthreads();

    // One tile per thread: tx = tid>>5 (0..7), ty = tid&31 (0..31). Tile 64x16.
    // Center (tx*64+31.5, ty*16+7.5); max px-to-center dist sqrt(31.5^2+7.5^2)
    // = 32.38 < 33. Segment in mask iff dist(center,seg) < thick + 33.
    const float cx = (float)((tid >> 5) << 6) + 31.5f;
    const float cy = (float)((tid & 31) << 4) + 7.5f;
    const float lim = s_thick + 33.0f;
    const float lim2 = lim * lim;

    unsigned int m = 0;
#pragma unroll
    for (int j = 0; j < NSEG; j++) {
        float ay = cy - s_vy[j];
        float ax = cx - s_vx[j];
        float dot = ay * s_dy[j] + ax * s_dx[j];
        float t = fminf(fmaxf(dot * s_id2[j], 0.f), 1.f);
        float ry = fmaf(-t, s_dy[j], ay);
        float rx = fmaf(-t, s_dx[j], ax);
        if (fmaf(ry, ry, rx * rx) < lim2) m |= (1u << j);
    }
    g_mask[b * 256 + tid] = m;    // tid == tx*32 + ty
}

// ---------------------------------------------------------------------------
// Render one 64x16 tile: 4 px/thread, 4 independent FMA chains.
// ---------------------------------------------------------------------------
__device__ __forceinline__ void render_tile(
    unsigned int mask, const SegParams* __restrict__ sp,
    float thick, float invthick, float yf, float x0, float* outp)
{
    float m0 = 1e30f, m1 = 1e30f, m2 = 1e30f, m3 = 1e30f;

    while (mask) {
        const int j = __ffs(mask) - 1;
        mask &= mask - 1;

        const float4 s  = __ldg(&sp->seg[j]);   // {vy, vx, dy, dx}
        const float ij  = __ldg(&sp->id2[j]);
        const float vjx = s.y, djy = s.z, djx = s.w;

        const float ay  = yf - s.x;
        const float cyd = ay * djy;

        {
            float pvx = x0 - vjx;
            float dot = fmaf(pvx, djx, cyd);
            float t   = fminf(fmaxf(dot * ij, 0.f), 1.f);
            float ry  = fmaf(-t, djy, ay);
            float rx  = fmaf(-t, djx, pvx);
            m0 = fminf(m0, fmaf(ry, ry, rx * rx));
        }
        {
            float pvx = x0 + 1.f - vjx;
            float dot = fmaf(pvx, djx, cyd);
            float t   = fminf(fmaxf(dot * ij, 0.f), 1.f);
            float ry  = fmaf(-t, djy, ay);
            float rx  = fmaf(-t, djx, pvx);
            m1 = fminf(m1, fmaf(ry, ry, rx * rx));
        }
        {
            float pvx = x0 + 2.f - vjx;
            float dot = fmaf(pvx, djx, cyd);
            float t   = fminf(fmaxf(dot * ij, 0.f), 1.f);
            float ry  = fmaf(-t, djy, ay);
            float rx  = fmaf(-t, djx, pvx);
            m2 = fminf(m2, fmaf(ry, ry, rx * rx));
        }
        {
            float pvx = x0 + 3.f - vjx;
            float dot = fmaf(pvx, djx, cyd);
            float t   = fminf(fmaxf(dot * ij, 0.f), 1.f);
            float ry  = fmaf(-t, djy, ay);
            float rx  = fmaf(-t, djx, pvx);
            m3 = fminf(m3, fmaf(ry, ry, rx * rx));
        }
    }

    float4 res;
    res.x = fminf(fmaxf((thick - sqrtf(m0)) * invthick, 0.f), 1.f);
    res.y = fminf(fmaxf((thick - sqrtf(m1)) * invthick, 0.f), 1.f);
    res.z = fminf(fmaxf((thick - sqrtf(m2)) * invthick, 0.f), 1.f);
    res.w = fminf(fmaxf((thick - sqrtf(m3)) * invthick, 0.f), 1.f);
    *reinterpret_cast<float4*>(outp) = res;
}

// ---------------------------------------------------------------------------
// K2: persistent render. Block bi: batch b = bi/74, idx = bi%74; owns tiles
// ttid = idx + k*74 (k = 0..3, ttid < 256). Zero-fill owned tiles before the
// PDL sync, then load all masks at once, then render active tiles.
// ---------------------------------------------------------------------------
__global__ void __launch_bounds__(256)
render_kernel(float* __restrict__ out)
{
    const int tid = threadIdx.x;
    const int b   = blockIdx.x / BPB;
    const int idx = blockIdx.x - b * BPB;

    const int px = (tid & 15) * 4;        // 0..60
    const int py = tid >> 4;              // 0..15
    float* outb = out + ((size_t)b << 18);

    // Owned tiles and their per-thread output pointers.
    int   nt = 0;
    int   ttids[4];
    float* outp[4];
#pragma unroll
    for (int k = 0; k < 4; k++) {
        const int ttid = idx + k * BPB;
        if (ttid < 256) {
            const int x = (((ttid >> 5)) << 6) + px;
            const int y = ((ttid & 31) << 4) + py;
            ttids[nt] = ttid;
            outp[nt]  = outb + ((size_t)y << 9) + x;
            nt++;
        }
    }

    // Speculative zero fill of all owned tiles — independent of setup.
    const float4 z = make_float4(0.f, 0.f, 0.f, 0.f);
#pragma unroll
    for (int k = 0; k < 4; k++)
        if (k < nt) *reinterpret_cast<float4*>(outp[k]) = z;

    // Wait for setup_kernel's results (PDL).
    cudaGridDependencySynchronize();

    // Issue all mask loads together (one exposed latency).
    unsigned int mk[4];
#pragma unroll
    for (int k = 0; k < 4; k++)
        mk[k] = (k < nt) ? __ldg(&g_mask[b * 256 + ttids[k]]) : 0u;

    const unsigned int any = mk[0] | mk[1] | mk[2] | mk[3];
    if (any == 0) return;

    const SegParams* sp = &g_params[b];
    const float thick    = __ldg(&sp->thick);
    const float invthick = __ldg(&sp->invthick);
    const float x0f = (float)px;

#pragma unroll
    for (int k = 0; k < 4; k++) {
        if (k < nt && mk[k]) {
            const int ttid = ttids[k];
            const float yf = (float)(((ttid & 31) << 4) + py);
            const float xf = (float)(((ttid >> 5) << 6)) + x0f;
            render_tile(mk[k], sp, thick, invthick, yf, xf, outp[k]);
        }
    }
}

extern "C" void kernel_launch(void* const* d_in, const int* in_sizes, int n_in,
                              void* d_out, int out_size)
{
    const float* traj = (const float*)d_in[0];   // (16, 2, 4)
    const float* thk  = (const float*)d_in[1];   // (16, 1, 4)
    float* out = (float*)d_out;                  // (16, 512, 512)

    setup_kernel<<<NBATCH, 256>>>(traj, thk);

    // Persistent render with Programmatic Dependent Launch: overlaps with
    // setup; waits (cudaGridDependencySynchronize) only before reading
    // setup's outputs.
    cudaLaunchConfig_t cfg = {};
    cfg.gridDim  = dim3(BPB * NBATCH, 1, 1);     // 1184 blocks = 1 wave
    cfg.blockDim = dim3(256, 1, 1);
    cfg.dynamicSmemBytes = 0;
    cfg.stream = 0;

    cudaLaunchAttribute attr[1];
    attr[0].id = cudaLaunchAttributeProgrammaticStreamSerialization;
    attr[0].val.programmaticStreamSerializationAllowed = 1;
    cfg.attrs = attr;
    cfg.numAttrs = 1;

    cudaLaunchKernelEx(&cfg, render_kernel, out);
}

// round 11
// speedup vs baseline: 1.2313x; 1.2313x over previous
#include <cuda_runtime.h>
#include <math.h>

// BezierRenderer: 16 batches, 512x512, 10 segments. SINGLE kernel.
// Grid (8,32,16), 256 threads, tile 64x16 px, 4 px (float4) per thread.
// Warp 0 computes the entire per-block setup (stroke points via exp2f, segment
// params, tile cull mask via ballot) in ~60 instructions; smem + one barrier
// hands it to the other warps. No second kernel, no global mask/param arrays.

#define NSEG  10
#define SIZEI 512

__global__ void __launch_bounds__(256)
bezier_kernel(const float* __restrict__ traj,
              const float* __restrict__ thk,
              float* __restrict__ out)
{
    __shared__ float4 s_seg[NSEG];      // {vy, vx, dy, dx}
    __shared__ float  s_id2[NSEG];
    __shared__ float  s_thick, s_invthick;
    __shared__ unsigned int s_mask;

    const int b   = blockIdx.z;
    const int tid = threadIdx.x;
    const int tx  = blockIdx.x;         // 0..7
    const int ty  = blockIdx.y;         // 0..31

    const int x = (tx << 6) + (tid & 15) * 4;
    const int y = (ty << 4) + (tid >> 4);
    float* outp = out + ((size_t)b << 18) + ((size_t)y << 9) + x;

    // Speculative zero fill — issues immediately, no dependencies.
    *reinterpret_cast<float4*>(outp) = make_float4(0.f, 0.f, 0.f, 0.f);

    // ---- warp 0: full setup ----
    if (tid < 32) {
        const int lane = tid;

        const float4 tyv = __ldg(reinterpret_cast<const float4*>(traj + b * 8));
        const float4 txv = __ldg(reinterpret_cast<const float4*>(traj + b * 8 + 4));
        const float4 tkv = __ldg(reinterpret_cast<const float4*>(thk + b * 4));

        // thick = 2 * sum(thk*2 + 0.5) over 4 ctrl
        const float th    = (tkv.x + tkv.y + tkv.z + tkv.w) * 2.f + 2.f;
        const float thick = 2.f * th;
        const float invthick = 1.f / thick;

        // Stroke point for this lane. Lanes 0..9: bezier-smoothed sample
        // using W[p][i] = 0.75*exp(-0.125*n_i^2), n_i = p - {-0.5,3.5,6.5,9.5}.
        // exp(-0.125 n^2) == exp2(-0.18033688 n^2)  ->  MUFU.EX2.
        float py, px;
        if (lane < NSEG) {
            const float p  = (float)lane;
            const float n0 = p + 0.5f, n1 = p - 3.5f, n2 = p - 6.5f, n3 = p - 9.5f;
            const float C  = -0.18033688f;    // -0.125 * log2(e)
            const float w0 = 0.75f * exp2f(C * n0 * n0);
            const float w1 = 0.75f * exp2f(C * n1 * n1);
            const float w2 = 0.75f * exp2f(C * n2 * n2);
            const float w3 = 0.75f * exp2f(C * n3 * n3);
            py = (w0 * tyv.x + w1 * tyv.y + w2 * tyv.z + w3 * tyv.w) * 512.f;
            px = (w0 * txv.x + w1 * txv.y + w2 * txv.z + w3 * txv.w) * 512.f;
        } else {                              // lane 10+ : the appended last point
            py = tyv.w * 512.f;
            px = txv.w * 512.f;
        }

        // Segment j: point j -> point j+1 (lane j+1 via shfl).
        const float py1 = __shfl_down_sync(0xFFFFFFFFu, py, 1);
        const float px1 = __shfl_down_sync(0xFFFFFFFFu, px, 1);
        const float dy  = py1 - py;
        const float dx  = px1 - px;
        const float id2 = 1.f / (dy * dy + dx * dx + 1e-5f);

        // Tile cull for segment `lane`: tile center (tx*64+31.5, ty*16+7.5);
        // max pixel-to-center distance sqrt(31.5^2+7.5^2)=32.38 < 33.
        // Segment contributes iff dist(center, seg) < thick + 33.
        const float cx = (float)(tx << 6) + 31.5f;
        const float cy = (float)(ty << 4) + 7.5f;
        const float lim = thick + 33.0f;
        const float ay = cy - py;
        const float ax = cx - px;
        const float dot = ay * dy + ax * dx;
        const float t   = fminf(fmaxf(dot * id2, 0.f), 1.f);
        const float ry  = fmaf(-t, dy, ay);
        const float rx  = fmaf(-t, dx, ax);
        const bool  act = (lane < NSEG) && (fmaf(ry, ry, rx * rx) < lim * lim);
        const unsigned int m = __ballot_sync(0xFFFFFFFFu, act);

        if (lane < NSEG) {
            s_seg[lane] = make_float4(py, px, dy, dx);
            s_id2[lane] = id2;
        }
        if (lane == 0) {
            s_thick = thick;
            s_invthick = invthick;
            s_mask = m;
        }
    }
    __syncthreads();

    unsigned int mask = s_mask;                // uniform
    if (mask == 0) return;                     // zeros already stored

    const float thick    = s_thick;
    const float invthick = s_invthick;
    const float yf = (float)y;
    const float x0 = (float)x;

    float m0 = 1e30f, m1 = 1e30f, m2 = 1e30f, m3 = 1e30f;

    while (mask) {
        const int j = __ffs(mask) - 1;
        mask &= mask - 1;

        const float4 s  = s_seg[j];            // LDS.128 broadcast
        const float ij  = s_id2[j];
        const float vjx = s.y, djy = s.z, djx = s.w;

        const float ay  = yf - s.x;            // same for all 4 px (same row)
        const float cyd = ay * djy;

        {
            float pvx = x0 - vjx;
            float dot = fmaf(pvx, djx, cyd);
            float t   = fminf(fmaxf(dot * ij, 0.f), 1.f);
            float ry  = fmaf(-t, djy, ay);
            float rx  = fmaf(-t, djx, pvx);
            m0 = fminf(m0, fmaf(ry, ry, rx * rx));
        }
        {
            float pvx = x0 + 1.f - vjx;
            float dot = fmaf(pvx, djx, cyd);
            float t   = fminf(fmaxf(dot * ij, 0.f), 1.f);
            float ry  = fmaf(-t, djy, ay);
            float rx  = fmaf(-t, djx, pvx);
            m1 = fminf(m1, fmaf(ry, ry, rx * rx));
        }
        {
            float pvx = x0 + 2.f - vjx;
            float dot = fmaf(pvx, djx, cyd);
            float t   = fminf(fmaxf(dot * ij, 0.f), 1.f);
            float ry  = fmaf(-t, djy, ay);
            float rx  = fmaf(-t, djx, pvx);
            m2 = fminf(m2, fmaf(ry, ry, rx * rx));
        }
        {
            float pvx = x0 + 3.f - vjx;
            float dot = fmaf(pvx, djx, cyd);
            float t   = fminf(fmaxf(dot * ij, 0.f), 1.f);
            float ry  = fmaf(-t, djy, ay);
            float rx  = fmaf(-t, djx, pvx);
            m3 = fminf(m3, fmaf(ry, ry, rx * rx));
        }
    }

    float4 res;
    res.x = fminf(fmaxf((thick - sqrtf(m0)) * invthick, 0.f), 1.f);
    res.y = fminf(fmaxf((thick - sqrtf(m1)) * invthick, 0.f), 1.f);
    res.z = fminf(fmaxf((thick - sqrtf(m2)) * invthick, 0.f), 1.f);
    res.w = fminf(fmaxf((thick - sqrtf(m3)) * invthick, 0.f), 1.f);

    *reinterpret_cast<float4*>(outp) = res;
}

extern "C" void kernel_launch(void* const* d_in, const int* in_sizes, int n_in,
                              void* d_out, int out_size)
{
    const float* traj = (const float*)d_in[0];   // (16, 2, 4)
    const float* thk  = (const float*)d_in[1];   // (16, 1, 4)
    float* out = (float*)d_out;                  // (16, 512, 512)

    dim3 grid(8, 32, 16);                        // 4096 blocks
    bezier_kernel<<<grid, 256>>>(traj, thk, out);
}

// round 13
// speedup vs baseline: 1.3221x; 1.0738x over previous
#include <cuda_runtime.h>
#include <math.h>

// BezierRenderer: 16 batches, 512x512, 10 segments. SINGLE kernel.
// Grid (8,16,16) = 2048 blocks, 256 threads. Tile 64x32 px; each thread owns
// 8 px: float4 at (x, y) and (x, y+16). Warp 0 computes the whole per-block
// setup (stroke points via exp2f, segment params, 64x32 tile cull via ballot);
// smem + one barrier. 8 independent FMA chains per segment iteration.

#define NSEG  10
#define SIZEI 512

__global__ void __launch_bounds__(256)
bezier_kernel(const float* __restrict__ traj,
              const float* __restrict__ thk,
              float* __restrict__ out)
{
    __shared__ float4 s_seg[NSEG];      // {vy, vx, dy, dx}
    __shared__ float  s_id2[NSEG];
    __shared__ float  s_thick, s_invthick;
    __shared__ unsigned int s_mask;

    const int b   = blockIdx.z;
    const int tid = threadIdx.x;
    const int tx  = blockIdx.x;         // 0..7   (64 px wide)
    const int ty  = blockIdx.y;         // 0..15  (32 px tall)

    const int x  = (tx << 6) + (tid & 15) * 4;
    const int y0 = (ty << 5) + (tid >> 4);           // rows y0 and y0+16
    float* outp0 = out + ((size_t)b << 18) + ((size_t)y0 << 9) + x;
    float* outp1 = outp0 + 16 * SIZEI;

    // Speculative zero fill — issues immediately, no dependencies.
    const float4 z = make_float4(0.f, 0.f, 0.f, 0.f);
    *reinterpret_cast<float4*>(outp0) = z;
    *reinterpret_cast<float4*>(outp1) = z;

    // ---- warp 0: full setup ----
    if (tid < 32) {
        const int lane = tid;

        const float4 tyv = __ldg(reinterpret_cast<const float4*>(traj + b * 8));
        const float4 txv = __ldg(reinterpret_cast<const float4*>(traj + b * 8 + 4));
        const float4 tkv = __ldg(reinterpret_cast<const float4*>(thk + b * 4));

        // thick = 2 * sum(thk*2 + 0.5) over 4 ctrl
        const float th    = (tkv.x + tkv.y + tkv.z + tkv.w) * 2.f + 2.f;
        const float thick = 2.f * th;
        const float invthick = 1.f / thick;

        // Stroke point for this lane. Lanes 0..9: gaussian-weighted sample,
        // W[p][i] = 0.75*exp(-0.125*n_i^2), n_i = p - {-0.5,3.5,6.5,9.5}.
        // exp(-0.125 n^2) == exp2(-0.18033688 n^2) -> MUFU.EX2.
        float py, px;
        if (lane < NSEG) {
            const float p  = (float)lane;
            const float n0 = p + 0.5f, n1 = p - 3.5f, n2 = p - 6.5f, n3 = p - 9.5f;
            const float C  = -0.18033688f;    // -0.125 * log2(e)
            const float w0 = 0.75f * exp2f(C * n0 * n0);
            const float w1 = 0.75f * exp2f(C * n1 * n1);
            const float w2 = 0.75f * exp2f(C * n2 * n2);
            const float w3 = 0.75f * exp2f(C * n3 * n3);
            py = (w0 * tyv.x + w1 * tyv.y + w2 * tyv.z + w3 * tyv.w) * 512.f;
            px = (w0 * txv.x + w1 * txv.y + w2 * txv.z + w3 * txv.w) * 512.f;
        } else {                              // appended last point
            py = tyv.w * 512.f;
            px = txv.w * 512.f;
        }

        // Segment j: point j -> j+1 (from lane j+1 via shfl).
        const float py1 = __shfl_down_sync(0xFFFFFFFFu, py, 1);
        const float px1 = __shfl_down_sync(0xFFFFFFFFu, px, 1);
        const float dy  = py1 - py;
        const float dx  = px1 - px;
        const float id2 = 1.f / (dy * dy + dx * dx + 1e-5f);

        // Cull for segment `lane` against this 64x32 tile:
        // center (tx*64+31.5, ty*32+15.5); max pixel-to-center distance
        // sqrt(31.5^2+15.5^2) = 35.11 < 35.2.
        const float cx = (float)(tx << 6) + 31.5f;
        const float cy = (float)(ty << 5) + 15.5f;
        const float lim = thick + 35.2f;
        const float ay = cy - py;
        const float ax = cx - px;
        const float dot = ay * dy + ax * dx;
        const float t   = fminf(fmaxf(dot * id2, 0.f), 1.f);
        const float ry  = fmaf(-t, dy, ay);
        const float rx  = fmaf(-t, dx, ax);
        const bool  act = (lane < NSEG) && (fmaf(ry, ry, rx * rx) < lim * lim);
        const unsigned int m = __ballot_sync(0xFFFFFFFFu, act);

        if (lane < NSEG) {
            s_seg[lane] = make_float4(py, px, dy, dx);
            s_id2[lane] = id2;
        }
        if (lane == 0) {
            s_thick = thick;
            s_invthick = invthick;
            s_mask = m;
        }
    }
    __syncthreads();

    unsigned int mask = s_mask;                // uniform
    if (mask == 0) return;                     // zeros already stored

    const float thick    = s_thick;
    const float invthick = s_invthick;
    const float yf0 = (float)y0;
    const float yf1 = (float)(y0 + 16);
    const float x0  = (float)x;

    float a0 = 1e30f, a1 = 1e30f, a2 = 1e30f, a3 = 1e30f;   // row y0
    float b0 = 1e30f, b1 = 1e30f, b2 = 1e30f, b3 = 1e30f;   // row y0+16

    while (mask) {
        const int j = __ffs(mask) - 1;
        mask &= mask - 1;

        const float4 s  = s_seg[j];            // LDS.128 broadcast
        const float ij  = s_id2[j];
        const float vjx = s.y, djy = s.z, djx = s.w;

        const float ayA  = yf0 - s.x;
        const float ayB  = yf1 - s.x;
        const float cydA = ayA * djy;
        const float cydB = ayB * djy;

#pragma unroll
        for (int c = 0; c < 4; c++) {
            const float pvx = (x0 + (float)c) - vjx;
            const float pd  = pvx * djx;
            // row A
            {
                float dot = pd + cydA;
                float t   = fminf(fmaxf(dot * ij, 0.f), 1.f);
                float ry  = fmaf(-t, djy, ayA);
                float rx  = fmaf(-t, djx, pvx);
                float dd  = fmaf(ry, ry, rx * rx);
                if (c == 0) a0 = fminf(a0, dd);
                if (c == 1) a1 = fminf(a1, dd);
                if (c == 2) a2 = fminf(a2, dd);
                if (c == 3) a3 = fminf(a3, dd);
            }
            // row B
            {
                float dot = pd + cydB;
                float t   = fminf(fmaxf(dot * ij, 0.f), 1.f);
                float ry  = fmaf(-t, djy, ayB);
                float rx  = fmaf(-t, djx, pvx);
                float dd  = fmaf(ry, ry, rx * rx);
                if (c == 0) b0 = fminf(b0, dd);
                if (c == 1) b1 = fminf(b1, dd);
                if (c == 2) b2 = fminf(b2, dd);
                if (c == 3) b3 = fminf(b3, dd);
            }
        }
    }

    float4 r0, r1;
    r0.x = fminf(fmaxf((thick - sqrtf(a0)) * invthick, 0.f), 1.f);
    r0.y = fminf(fmaxf((thick - sqrtf(a1)) * invthick, 0.f), 1.f);
    r0.z = fminf(fmaxf((thick - sqrtf(a2)) * invthick, 0.f), 1.f);
    r0.w = fminf(fmaxf((thick - sqrtf(a3)) * invthick, 0.f), 1.f);
    r1.x = fminf(fmaxf((thick - sqrtf(b0)) * invthick, 0.f), 1.f);
    r1.y = fminf(fmaxf((thick - sqrtf(b1)) * invthick, 0.f), 1.f);
    r1.z = fminf(fmaxf((thick - sqrtf(b2)) * invthick, 0.f), 1.f);
    r1.w = fminf(fmaxf((thick - sqrtf(b3)) * invthick, 0.f), 1.f);

    *reinterpret_cast<float4*>(outp0) = r0;
    *reinterpret_cast<float4*>(outp1) = r1;
}

extern "C" void kernel_launch(void* const* d_in, const int* in_sizes, int n_in,
                              void* d_out, int out_size)
{
    const float* traj = (const float*)d_in[0];   // (16, 2, 4)
    const float* thk  = (const float*)d_in[1];   // (16, 1, 4)
    float* out = (float*)d_out;                  // (16, 512, 512)

    dim3 grid(8, 16, 16);                        // 2048 blocks
    bezier_kernel<<<grid, 256>>>(traj, thk, out);
}